// round 3
// baseline (speedup 1.0000x reference)
#include <cuda_runtime.h>

using ull = unsigned long long;

#define R 3

// ---------------- f32x2 packed-math helpers (Blackwell FFMA2 path) ----------------

__device__ __forceinline__ ull ffma2(ull a, ull b, ull c) {
    ull d;
    asm("fma.rn.f32x2 %0, %1, %2, %3;" : "=l"(d) : "l"(a), "l"(b), "l"(c));
    return d;
}
__device__ __forceinline__ ull pk2(float x, float y) {
    ull r;
    asm("mov.b64 %0, {%1, %2};" : "=l"(r) : "f"(x), "f"(y));
    return r;
}
__device__ __forceinline__ void unpk2(ull v, float& x, float& y) {
    asm("mov.b64 {%0, %1}, %2;" : "=f"(x), "=f"(y) : "l"(v));
}

// ---------------- shared-memory weight cache (masks + interleave baked) ----------------

struct __align__(16) Smem {
    float W1[4 * 64];
    float B1[64];
    float W2[64 * 32];
    float B2[32];
    float W3[32 * 8];
    float B3[8];
    float Pj[16];          // proj: interleaved {w[i][0], w[i][1]} pairs
    float Pc[8];           // proj: w[i][2]
    float Fh[10 * 64];     // flow hidden: [l][input(2)][32], input-1 row mask-baked
    float Fbh[10 * 32];
    float FoA[10 * 32];    // per layer 16 pairs: {wmu1[2j], wa1[2j]} (even units; odd masked to 0)
    float FoB[10 * 64];    // per layer 32 pairs: {wmu2[k], wa2[k]} (all units)
    float Fb[10 * 6 + 4];  // [l] = {bmu0, exp(-tanh(ba0)), bmu1, ba1, bmu2, ba2}
    float Pb[4];
};

__global__ __launch_bounds__(128)
void gsi_kernel(const float* __restrict__ states,
                const float* __restrict__ enc_w1, const float* __restrict__ enc_b1,
                const float* __restrict__ enc_w2, const float* __restrict__ enc_b2,
                const float* __restrict__ enc_w3, const float* __restrict__ enc_b3,
                const float* __restrict__ proj_w, const float* __restrict__ proj_b,
                const float* __restrict__ flow_wh, const float* __restrict__ flow_bh,
                const float* __restrict__ flow_wmu, const float* __restrict__ flow_bmu,
                const float* __restrict__ flow_wa, const float* __restrict__ flow_ba,
                float* __restrict__ out, int B) {
    __shared__ Smem sm;
    const int tid = threadIdx.x;

    // ---- cooperative weight load + mask/interleave bake ----
    for (int i = tid; i < 4 * 64; i += 128)  sm.W1[i] = enc_w1[i];
    for (int i = tid; i < 64;     i += 128)  sm.B1[i] = enc_b1[i];
    for (int i = tid; i < 64 * 32; i += 128) sm.W2[i] = enc_w2[i];
    for (int i = tid; i < 32;     i += 128)  sm.B2[i] = enc_b2[i];
    for (int i = tid; i < 32 * 8; i += 128)  sm.W3[i] = enc_w3[i];
    for (int i = tid; i < 8;      i += 128)  sm.B3[i] = enc_b3[i];
    if (tid < 8) {
        sm.Pj[2 * tid]     = proj_w[tid * 3 + 0];
        sm.Pj[2 * tid + 1] = proj_w[tid * 3 + 1];
        sm.Pc[tid]         = proj_w[tid * 3 + 2];
    }
    if (tid < 3) sm.Pb[tid] = proj_b[tid];
    if (tid == 3) sm.Pb[3] = 0.f;
    // flow hidden: m_h[0][j]=1 all j; m_h[1][j]=1 iff j odd; m_h[2][:]=0 (dropped)
    for (int i = tid; i < 10 * 32; i += 128) {
        int l = i >> 5, j = i & 31;
        sm.Fh[l * 64 + j]      = flow_wh[l * 96 + j];
        sm.Fh[l * 64 + 32 + j] = (j & 1) ? flow_wh[l * 96 + 32 + j] : 0.f;
        sm.Fbh[i] = flow_bh[i];
    }
    // flow output: m_o[k][1]=1 iff k even; m_o[k][2]=1; m_o[k][0]=0 (out0 = pure bias)
    for (int i = tid; i < 10 * 16; i += 128) {
        int l = i >> 4, j = i & 15;
        int base = l * 96 + (2 * j) * 3;
        sm.FoA[l * 32 + 2 * j]     = flow_wmu[base + 1];
        sm.FoA[l * 32 + 2 * j + 1] = flow_wa[base + 1];
    }
    for (int i = tid; i < 10 * 32; i += 128) {
        int l = i >> 5, k = i & 31;
        int base = l * 96 + k * 3;
        sm.FoB[l * 64 + 2 * k]     = flow_wmu[base + 2];
        sm.FoB[l * 64 + 2 * k + 1] = flow_wa[base + 2];
    }
    if (tid < 10) {
        int l = tid;
        sm.Fb[l * 6 + 0] = flow_bmu[l * 3 + 0];
        sm.Fb[l * 6 + 1] = expf(-tanhf(flow_ba[l * 3 + 0]));
        sm.Fb[l * 6 + 2] = flow_bmu[l * 3 + 1];
        sm.Fb[l * 6 + 3] = flow_ba[l * 3 + 1];
        sm.Fb[l * 6 + 4] = flow_bmu[l * 3 + 2];
        sm.Fb[l * 6 + 5] = flow_ba[l * 3 + 2];
    }
    __syncthreads();

    // ---- R rows per thread: every weight LDS amortized over all R ----
    int r[R];
    bool vv[R];
    float4 s[R];
#pragma unroll
    for (int q = 0; q < R; q++) {
        r[q] = blockIdx.x * (128 * R) + q * 128 + tid;
        vv[q] = r[q] < B;
        s[q] = vv[q] ? reinterpret_cast<const float4*>(states)[r[q]]
                     : make_float4(0.f, 0.f, 0.f, 0.f);
    }

    // ---- fused enc1 (4->64) + enc2 (64->32), chunked 8 hidden units at a time ----
    ull h2[R][16];
    {
        const ulonglong2* pb = reinterpret_cast<const ulonglong2*>(sm.B2);
#pragma unroll
        for (int p = 0; p < 8; p++) {
            ulonglong2 v = pb[p];
#pragma unroll
            for (int q = 0; q < R; q++) { h2[q][2 * p] = v.x; h2[q][2 * p + 1] = v.y; }
        }
    }
    ull xp[R][4];
#pragma unroll
    for (int q = 0; q < R; q++) {
        xp[q][0] = pk2(s[q].x, s[q].x); xp[q][1] = pk2(s[q].y, s[q].y);
        xp[q][2] = pk2(s[q].z, s[q].z); xp[q][3] = pk2(s[q].w, s[q].w);
    }

#pragma unroll 1
    for (int c = 0; c < 8; c++) {
        ull h1[R][4];
        const ulonglong2* pb1 = reinterpret_cast<const ulonglong2*>(sm.B1 + c * 8);
#pragma unroll
        for (int p = 0; p < 2; p++) {
            ulonglong2 v = pb1[p];
#pragma unroll
            for (int q = 0; q < R; q++) { h1[q][2 * p] = v.x; h1[q][2 * p + 1] = v.y; }
        }
#pragma unroll
        for (int i = 0; i < 4; i++) {
            const ulonglong2* w = reinterpret_cast<const ulonglong2*>(sm.W1 + i * 64 + c * 8);
#pragma unroll
            for (int p = 0; p < 2; p++) {
                ulonglong2 v = w[p];
#pragma unroll
                for (int q = 0; q < R; q++) {
                    h1[q][2 * p]     = ffma2(xp[q][i], v.x, h1[q][2 * p]);
                    h1[q][2 * p + 1] = ffma2(xp[q][i], v.y, h1[q][2 * p + 1]);
                }
            }
        }
        // consume this chunk into h2
#pragma unroll
        for (int j = 0; j < 4; j++) {
            ull ab[R], bb[R];
#pragma unroll
            for (int q = 0; q < R; q++) {
                float a, b;
                unpk2(h1[q][j], a, b);
                a = fmaxf(a, 0.f); b = fmaxf(b, 0.f);
                ab[q] = pk2(a, a); bb[q] = pk2(b, b);
            }
            const int u = c * 8 + 2 * j;
            const ulonglong2* wa = reinterpret_cast<const ulonglong2*>(sm.W2 + u * 32);
            const ulonglong2* wb = reinterpret_cast<const ulonglong2*>(sm.W2 + u * 32 + 32);
#pragma unroll
            for (int p = 0; p < 8; p++) {
                ulonglong2 v = wa[p];
#pragma unroll
                for (int q = 0; q < R; q++) {
                    h2[q][2 * p]     = ffma2(ab[q], v.x, h2[q][2 * p]);
                    h2[q][2 * p + 1] = ffma2(ab[q], v.y, h2[q][2 * p + 1]);
                }
            }
#pragma unroll
            for (int p = 0; p < 8; p++) {
                ulonglong2 v = wb[p];
#pragma unroll
                for (int q = 0; q < R; q++) {
                    h2[q][2 * p]     = ffma2(bb[q], v.x, h2[q][2 * p]);
                    h2[q][2 * p + 1] = ffma2(bb[q], v.y, h2[q][2 * p + 1]);
                }
            }
        }
    }

    // ---- enc3: 32 -> 8 ----
    ull cp[R][4];
    {
        const ulonglong2* pb = reinterpret_cast<const ulonglong2*>(sm.B3);
        ulonglong2 v0b = pb[0], v1b = pb[1];
#pragma unroll
        for (int q = 0; q < R; q++) {
            cp[q][0] = v0b.x; cp[q][1] = v0b.y; cp[q][2] = v1b.x; cp[q][3] = v1b.y;
        }
    }
#pragma unroll
    for (int j = 0; j < 16; j++) {
        ull ab[R], bb[R];
#pragma unroll
        for (int q = 0; q < R; q++) {
            float a, b;
            unpk2(h2[q][j], a, b);
            a = fmaxf(a, 0.f); b = fmaxf(b, 0.f);
            ab[q] = pk2(a, a); bb[q] = pk2(b, b);
        }
        const ulonglong2* wa = reinterpret_cast<const ulonglong2*>(sm.W3 + (2 * j) * 8);
        const ulonglong2* wb = reinterpret_cast<const ulonglong2*>(sm.W3 + (2 * j + 1) * 8);
        ulonglong2 va0 = wa[0], va1 = wa[1];
        ulonglong2 vb0 = wb[0], vb1 = wb[1];
#pragma unroll
        for (int q = 0; q < R; q++) {
            cp[q][0] = ffma2(ab[q], va0.x, cp[q][0]); cp[q][1] = ffma2(ab[q], va0.y, cp[q][1]);
            cp[q][2] = ffma2(ab[q], va1.x, cp[q][2]); cp[q][3] = ffma2(ab[q], va1.y, cp[q][3]);
            cp[q][0] = ffma2(bb[q], vb0.x, cp[q][0]); cp[q][1] = ffma2(bb[q], vb0.y, cp[q][1]);
            cp[q][2] = ffma2(bb[q], vb1.x, cp[q][2]); cp[q][3] = ffma2(bb[q], vb1.y, cp[q][3]);
        }
    }

    // ---- projection 8 -> 3 ----
    ull a01[R];
    float x2[R], x0[R], x1[R];
#pragma unroll
    for (int q = 0; q < R; q++) { a01[q] = pk2(sm.Pb[0], sm.Pb[1]); x2[q] = sm.Pb[2]; }
#pragma unroll
    for (int jj = 0; jj < 4; jj++) {
#pragma unroll
        for (int q = 0; q < R; q++) {
            float cc0, cc1;
            unpk2(cp[q][jj], cc0, cc1);
            ull w0 = reinterpret_cast<const ull*>(sm.Pj)[2 * jj];
            ull w1 = reinterpret_cast<const ull*>(sm.Pj)[2 * jj + 1];
            a01[q] = ffma2(pk2(cc0, cc0), w0, a01[q]);
            a01[q] = ffma2(pk2(cc1, cc1), w1, a01[q]);
            x2[q] = fmaf(cc0, sm.Pc[2 * jj], x2[q]);
            x2[q] = fmaf(cc1, sm.Pc[2 * jj + 1], x2[q]);
        }
    }
#pragma unroll
    for (int q = 0; q < R; q++) unpk2(a01[q], x0[q], x1[q]);

    // ---- MAF flow: 10 masked affine-AR layers + flip ----
#pragma unroll 1
    for (int l = 0; l < 10; l++) {
        const float* fh  = sm.Fh  + l * 64;
        const float* fbh = sm.Fbh + l * 32;
        const float* foA = sm.FoA + l * 32;
        const float* foB = sm.FoB + l * 64;
        const float* fb  = sm.Fb  + l * 6;

        ull hh[R][16];
        const ulonglong2* pbh = reinterpret_cast<const ulonglong2*>(fbh);
#pragma unroll
        for (int p = 0; p < 8; p++) {
            ulonglong2 v = pbh[p];
#pragma unroll
            for (int q = 0; q < R; q++) { hh[q][2 * p] = v.x; hh[q][2 * p + 1] = v.y; }
        }
        ull x0b[R], x1b[R];
#pragma unroll
        for (int q = 0; q < R; q++) { x0b[q] = pk2(x0[q], x0[q]); x1b[q] = pk2(x1[q], x1[q]); }
        const ulonglong2* w0 = reinterpret_cast<const ulonglong2*>(fh);
        const ulonglong2* w1 = reinterpret_cast<const ulonglong2*>(fh + 32);
#pragma unroll
        for (int p = 0; p < 8; p++) {
            ulonglong2 v = w0[p];
#pragma unroll
            for (int q = 0; q < R; q++) {
                hh[q][2 * p]     = ffma2(x0b[q], v.x, hh[q][2 * p]);
                hh[q][2 * p + 1] = ffma2(x0b[q], v.y, hh[q][2 * p + 1]);
            }
        }
#pragma unroll
        for (int p = 0; p < 8; p++) {
            ulonglong2 v = w1[p];
#pragma unroll
            for (int q = 0; q < R; q++) {
                hh[q][2 * p]     = ffma2(x1b[q], v.x, hh[q][2 * p]);
                hh[q][2 * p + 1] = ffma2(x1b[q], v.y, hh[q][2 * p + 1]);
            }
        }

        ull acc1[R], acc2[R];
#pragma unroll
        for (int q = 0; q < R; q++) {
            acc1[q] = pk2(fb[2], fb[3]);
            acc2[q] = pk2(fb[4], fb[5]);
        }
#pragma unroll
        for (int j = 0; j < 16; j++) {
            ull wv = reinterpret_cast<const ull*>(foA)[j];
            ulonglong2 wv2 = reinterpret_cast<const ulonglong2*>(foB)[j];
#pragma unroll
            for (int q = 0; q < R; q++) {
                float a, b;
                unpk2(hh[q][j], a, b);
                a = fmaxf(a, 0.f); b = fmaxf(b, 0.f);
                ull ab = pk2(a, a), bb = pk2(b, b);
                acc1[q] = ffma2(ab, wv, acc1[q]);
                acc2[q] = ffma2(ab, wv2.x, acc2[q]);
                acc2[q] = ffma2(bb, wv2.y, acc2[q]);
            }
        }
        float bmu0 = fb[0], esc0 = fb[1];
#pragma unroll
        for (int q = 0; q < R; q++) {
            float mu1, al1, mu2, al2;
            unpk2(acc1[q], mu1, al1); unpk2(acc2[q], mu2, al2);
            float t1 = 1.f - __fdividef(2.f, __expf(2.f * al1) + 1.f);
            float t2 = 1.f - __fdividef(2.f, __expf(2.f * al2) + 1.f);
            float nx0 = (x0[q] - bmu0) * esc0;
            float nx1 = (x1[q] - mu1) * __expf(-t1);
            float nx2 = (x2[q] - mu2) * __expf(-t2);
            x0[q] = nx2; x1[q] = nx1; x2[q] = nx0;
        }
    }

    // ---- squash + HSV + store ----
#pragma unroll
    for (int q = 0; q < R; q++) {
        if (vv[q]) {
            float u0 = __fdividef(1.f, 1.f + __expf(-x0[q]));
            float u1 = __fdividef(1.f, 1.f + __expf(-x1[q]));
            float u2 = __fdividef(1.f, 1.f + __expf(-x2[q]));
            out[3 * r[q] + 0] = 6.2831853071795864769f * u0;
            out[3 * r[q] + 1] = u1;
            out[3 * r[q] + 2] = u2;
        }
    }
}

extern "C" void kernel_launch(void* const* d_in, const int* in_sizes, int n_in,
                              void* d_out, int out_size) {
    (void)n_in; (void)out_size;
    const float* states   = (const float*)d_in[0];
    const float* enc_w1   = (const float*)d_in[1];
    const float* enc_b1   = (const float*)d_in[2];
    const float* enc_w2   = (const float*)d_in[3];
    const float* enc_b2   = (const float*)d_in[4];
    const float* enc_w3   = (const float*)d_in[5];
    const float* enc_b3   = (const float*)d_in[6];
    const float* proj_w   = (const float*)d_in[7];
    const float* proj_b   = (const float*)d_in[8];
    const float* flow_wh  = (const float*)d_in[9];
    const float* flow_bh  = (const float*)d_in[10];
    const float* flow_wmu = (const float*)d_in[11];
    const float* flow_bmu = (const float*)d_in[12];
    const float* flow_wa  = (const float*)d_in[13];
    const float* flow_ba  = (const float*)d_in[14];

    const int B = in_sizes[0] / 4;
    const int grid = (B + 128 * R - 1) / (128 * R);
    gsi_kernel<<<grid, 128>>>(states, enc_w1, enc_b1, enc_w2, enc_b2, enc_w3, enc_b3,
                              proj_w, proj_b, flow_wh, flow_bh, flow_wmu, flow_bmu,
                              flow_wa, flow_ba, (float*)d_out, B);
}

// round 4
// speedup vs baseline: 1.0527x; 1.0527x over previous
#include <cuda_runtime.h>

using ull = unsigned long long;

#define R 3

// ---------------- f32x2 packed-math helpers (Blackwell FFMA2 path) ----------------

__device__ __forceinline__ ull ffma2(ull a, ull b, ull c) {
    ull d;
    asm("fma.rn.f32x2 %0, %1, %2, %3;" : "=l"(d) : "l"(a), "l"(b), "l"(c));
    return d;
}
__device__ __forceinline__ ull pk2(float x, float y) {
    ull r;
    asm("mov.b64 %0, {%1, %2};" : "=l"(r) : "f"(x), "f"(y));
    return r;
}
__device__ __forceinline__ void unpk2(ull v, float& x, float& y) {
    asm("mov.b64 {%0, %1}, %2;" : "=f"(x), "=f"(y) : "l"(v));
}
__device__ __forceinline__ float tanh_fast(float x) {
    float y;
    asm("tanh.approx.f32 %0, %1;" : "=f"(y) : "f"(x));
    return y;
}

// ---------------- shared-memory weight cache (masks + interleave baked) ----------------

struct __align__(16) Smem {
    float W1[4 * 64];
    float B1[64];
    float W2[64 * 32];
    float B2[32];
    float W3[32 * 8];
    float B3[8];
    float Pj[16];          // proj: interleaved {w[i][0], w[i][1]} pairs
    float Pc[8];           // proj: w[i][2]
    float Fh[10 * 64];     // flow hidden: [l][input(2)][32], input-1 row mask-baked
    float Fbh[10 * 32];
    float FoA[10 * 32];    // per layer 16 pairs: {wmu1[2j], wa1[2j]} (even units; odd masked to 0)
    float FoB[10 * 64];    // per layer 32 pairs: {wmu2[k], wa2[k]} (all units)
    float Fb[10 * 6 + 4];  // [l] = {bmu0, exp(-tanh(ba0)), bmu1, ba1, bmu2, ba2}
    float Pb[4];
};

__global__ __launch_bounds__(128, 3)
void gsi_kernel(const float* __restrict__ states,
                const float* __restrict__ enc_w1, const float* __restrict__ enc_b1,
                const float* __restrict__ enc_w2, const float* __restrict__ enc_b2,
                const float* __restrict__ enc_w3, const float* __restrict__ enc_b3,
                const float* __restrict__ proj_w, const float* __restrict__ proj_b,
                const float* __restrict__ flow_wh, const float* __restrict__ flow_bh,
                const float* __restrict__ flow_wmu, const float* __restrict__ flow_bmu,
                const float* __restrict__ flow_wa, const float* __restrict__ flow_ba,
                float* __restrict__ out, int B) {
    __shared__ Smem sm;
    const int tid = threadIdx.x;

    // ---- cooperative weight load + mask/interleave bake ----
    for (int i = tid; i < 4 * 64; i += 128)  sm.W1[i] = enc_w1[i];
    for (int i = tid; i < 64;     i += 128)  sm.B1[i] = enc_b1[i];
    for (int i = tid; i < 64 * 32; i += 128) sm.W2[i] = enc_w2[i];
    for (int i = tid; i < 32;     i += 128)  sm.B2[i] = enc_b2[i];
    for (int i = tid; i < 32 * 8; i += 128)  sm.W3[i] = enc_w3[i];
    for (int i = tid; i < 8;      i += 128)  sm.B3[i] = enc_b3[i];
    if (tid < 8) {
        sm.Pj[2 * tid]     = proj_w[tid * 3 + 0];
        sm.Pj[2 * tid + 1] = proj_w[tid * 3 + 1];
        sm.Pc[tid]         = proj_w[tid * 3 + 2];
    }
    if (tid < 3) sm.Pb[tid] = proj_b[tid];
    if (tid == 3) sm.Pb[3] = 0.f;
    // flow hidden: m_h[0][j]=1 all j; m_h[1][j]=1 iff j odd; m_h[2][:]=0 (dropped)
    for (int i = tid; i < 10 * 32; i += 128) {
        int l = i >> 5, j = i & 31;
        sm.Fh[l * 64 + j]      = flow_wh[l * 96 + j];
        sm.Fh[l * 64 + 32 + j] = (j & 1) ? flow_wh[l * 96 + 32 + j] : 0.f;
        sm.Fbh[i] = flow_bh[i];
    }
    // flow output: m_o[k][1]=1 iff k even; m_o[k][2]=1; m_o[k][0]=0 (out0 = pure bias)
    for (int i = tid; i < 10 * 16; i += 128) {
        int l = i >> 4, j = i & 15;
        int base = l * 96 + (2 * j) * 3;
        sm.FoA[l * 32 + 2 * j]     = flow_wmu[base + 1];
        sm.FoA[l * 32 + 2 * j + 1] = flow_wa[base + 1];
    }
    for (int i = tid; i < 10 * 32; i += 128) {
        int l = i >> 5, k = i & 31;
        int base = l * 96 + k * 3;
        sm.FoB[l * 64 + 2 * k]     = flow_wmu[base + 2];
        sm.FoB[l * 64 + 2 * k + 1] = flow_wa[base + 2];
    }
    if (tid < 10) {
        int l = tid;
        sm.Fb[l * 6 + 0] = flow_bmu[l * 3 + 0];
        sm.Fb[l * 6 + 1] = expf(-tanhf(flow_ba[l * 3 + 0]));
        sm.Fb[l * 6 + 2] = flow_bmu[l * 3 + 1];
        sm.Fb[l * 6 + 3] = flow_ba[l * 3 + 1];
        sm.Fb[l * 6 + 4] = flow_bmu[l * 3 + 2];
        sm.Fb[l * 6 + 5] = flow_ba[l * 3 + 2];
    }
    __syncthreads();

    // ---- R rows per thread: every weight LDS amortized over all R ----
    const int rbase = blockIdx.x * (128 * R) + tid;

    // ---- fused enc1 (4->64) + enc2 (64->32), chunked 8 hidden units at a time ----
    ull h2[R][16];
    {
        const ulonglong2* pb = reinterpret_cast<const ulonglong2*>(sm.B2);
#pragma unroll
        for (int p = 0; p < 8; p++) {
            ulonglong2 v = pb[p];
#pragma unroll
            for (int q = 0; q < R; q++) { h2[q][2 * p] = v.x; h2[q][2 * p + 1] = v.y; }
        }
    }
    ull xp[R][4];
#pragma unroll
    for (int q = 0; q < R; q++) {
        int rl = rbase + q * 128;
        if (rl > B - 1) rl = B - 1;                      // clamp: safe load, store guarded later
        float4 sv = reinterpret_cast<const float4*>(states)[rl];
        xp[q][0] = pk2(sv.x, sv.x); xp[q][1] = pk2(sv.y, sv.y);
        xp[q][2] = pk2(sv.z, sv.z); xp[q][3] = pk2(sv.w, sv.w);
    }

#pragma unroll 1
    for (int c = 0; c < 8; c++) {
        ull h1[R][4];
        const ulonglong2* pb1 = reinterpret_cast<const ulonglong2*>(sm.B1 + c * 8);
#pragma unroll
        for (int p = 0; p < 2; p++) {
            ulonglong2 v = pb1[p];
#pragma unroll
            for (int q = 0; q < R; q++) { h1[q][2 * p] = v.x; h1[q][2 * p + 1] = v.y; }
        }
#pragma unroll
        for (int i = 0; i < 4; i++) {
            const ulonglong2* w = reinterpret_cast<const ulonglong2*>(sm.W1 + i * 64 + c * 8);
#pragma unroll
            for (int p = 0; p < 2; p++) {
                ulonglong2 v = w[p];
#pragma unroll
                for (int q = 0; q < R; q++) {
                    h1[q][2 * p]     = ffma2(xp[q][i], v.x, h1[q][2 * p]);
                    h1[q][2 * p + 1] = ffma2(xp[q][i], v.y, h1[q][2 * p + 1]);
                }
            }
        }
        // consume this chunk into h2
#pragma unroll
        for (int j = 0; j < 4; j++) {
            ull ab[R], bb[R];
#pragma unroll
            for (int q = 0; q < R; q++) {
                float a, b;
                unpk2(h1[q][j], a, b);
                a = fmaxf(a, 0.f); b = fmaxf(b, 0.f);
                ab[q] = pk2(a, a); bb[q] = pk2(b, b);
            }
            const int u = c * 8 + 2 * j;
            const ulonglong2* wa = reinterpret_cast<const ulonglong2*>(sm.W2 + u * 32);
            const ulonglong2* wb = reinterpret_cast<const ulonglong2*>(sm.W2 + u * 32 + 32);
#pragma unroll
            for (int p = 0; p < 8; p++) {
                ulonglong2 v = wa[p];
#pragma unroll
                for (int q = 0; q < R; q++) {
                    h2[q][2 * p]     = ffma2(ab[q], v.x, h2[q][2 * p]);
                    h2[q][2 * p + 1] = ffma2(ab[q], v.y, h2[q][2 * p + 1]);
                }
            }
#pragma unroll
            for (int p = 0; p < 8; p++) {
                ulonglong2 v = wb[p];
#pragma unroll
                for (int q = 0; q < R; q++) {
                    h2[q][2 * p]     = ffma2(bb[q], v.x, h2[q][2 * p]);
                    h2[q][2 * p + 1] = ffma2(bb[q], v.y, h2[q][2 * p + 1]);
                }
            }
        }
    }

    // ---- enc3: 32 -> 8 ----
    ull cp[R][4];
    {
        const ulonglong2* pb = reinterpret_cast<const ulonglong2*>(sm.B3);
        ulonglong2 v0b = pb[0], v1b = pb[1];
#pragma unroll
        for (int q = 0; q < R; q++) {
            cp[q][0] = v0b.x; cp[q][1] = v0b.y; cp[q][2] = v1b.x; cp[q][3] = v1b.y;
        }
    }
#pragma unroll
    for (int j = 0; j < 16; j++) {
        ull ab[R], bb[R];
#pragma unroll
        for (int q = 0; q < R; q++) {
            float a, b;
            unpk2(h2[q][j], a, b);
            a = fmaxf(a, 0.f); b = fmaxf(b, 0.f);
            ab[q] = pk2(a, a); bb[q] = pk2(b, b);
        }
        const ulonglong2* wa = reinterpret_cast<const ulonglong2*>(sm.W3 + (2 * j) * 8);
        const ulonglong2* wb = reinterpret_cast<const ulonglong2*>(sm.W3 + (2 * j + 1) * 8);
        ulonglong2 va0 = wa[0], va1 = wa[1];
        ulonglong2 vb0 = wb[0], vb1 = wb[1];
#pragma unroll
        for (int q = 0; q < R; q++) {
            cp[q][0] = ffma2(ab[q], va0.x, cp[q][0]); cp[q][1] = ffma2(ab[q], va0.y, cp[q][1]);
            cp[q][2] = ffma2(ab[q], va1.x, cp[q][2]); cp[q][3] = ffma2(ab[q], va1.y, cp[q][3]);
            cp[q][0] = ffma2(bb[q], vb0.x, cp[q][0]); cp[q][1] = ffma2(bb[q], vb0.y, cp[q][1]);
            cp[q][2] = ffma2(bb[q], vb1.x, cp[q][2]); cp[q][3] = ffma2(bb[q], vb1.y, cp[q][3]);
        }
    }

    // ---- projection 8 -> 3 ----
    ull a01[R];
    float x2[R], x0[R], x1[R];
#pragma unroll
    for (int q = 0; q < R; q++) { a01[q] = pk2(sm.Pb[0], sm.Pb[1]); x2[q] = sm.Pb[2]; }
#pragma unroll
    for (int jj = 0; jj < 4; jj++) {
        ull w0 = reinterpret_cast<const ull*>(sm.Pj)[2 * jj];
        ull w1 = reinterpret_cast<const ull*>(sm.Pj)[2 * jj + 1];
        float pc0 = sm.Pc[2 * jj], pc1 = sm.Pc[2 * jj + 1];
#pragma unroll
        for (int q = 0; q < R; q++) {
            float cc0, cc1;
            unpk2(cp[q][jj], cc0, cc1);
            a01[q] = ffma2(pk2(cc0, cc0), w0, a01[q]);
            a01[q] = ffma2(pk2(cc1, cc1), w1, a01[q]);
            x2[q] = fmaf(cc0, pc0, x2[q]);
            x2[q] = fmaf(cc1, pc1, x2[q]);
        }
    }
#pragma unroll
    for (int q = 0; q < R; q++) unpk2(a01[q], x0[q], x1[q]);

    // ---- MAF flow: 10 masked affine-AR layers + flip ----
#pragma unroll 1
    for (int l = 0; l < 10; l++) {
        const float* fh  = sm.Fh  + l * 64;
        const float* fbh = sm.Fbh + l * 32;
        const float* foA = sm.FoA + l * 32;
        const float* foB = sm.FoB + l * 64;
        const float* fb  = sm.Fb  + l * 6;

        ull hh[R][16];
        const ulonglong2* pbh = reinterpret_cast<const ulonglong2*>(fbh);
#pragma unroll
        for (int p = 0; p < 8; p++) {
            ulonglong2 v = pbh[p];
#pragma unroll
            for (int q = 0; q < R; q++) { hh[q][2 * p] = v.x; hh[q][2 * p + 1] = v.y; }
        }
        ull x0b[R], x1b[R];
#pragma unroll
        for (int q = 0; q < R; q++) { x0b[q] = pk2(x0[q], x0[q]); x1b[q] = pk2(x1[q], x1[q]); }
        const ulonglong2* w0 = reinterpret_cast<const ulonglong2*>(fh);
        const ulonglong2* w1 = reinterpret_cast<const ulonglong2*>(fh + 32);
#pragma unroll
        for (int p = 0; p < 8; p++) {
            ulonglong2 v = w0[p];
#pragma unroll
            for (int q = 0; q < R; q++) {
                hh[q][2 * p]     = ffma2(x0b[q], v.x, hh[q][2 * p]);
                hh[q][2 * p + 1] = ffma2(x0b[q], v.y, hh[q][2 * p + 1]);
            }
        }
#pragma unroll
        for (int p = 0; p < 8; p++) {
            ulonglong2 v = w1[p];
#pragma unroll
            for (int q = 0; q < R; q++) {
                hh[q][2 * p]     = ffma2(x1b[q], v.x, hh[q][2 * p]);
                hh[q][2 * p + 1] = ffma2(x1b[q], v.y, hh[q][2 * p + 1]);
            }
        }

        ull acc1[R], acc2[R];
#pragma unroll
        for (int q = 0; q < R; q++) {
            acc1[q] = pk2(fb[2], fb[3]);
            acc2[q] = pk2(fb[4], fb[5]);
        }
#pragma unroll
        for (int j = 0; j < 16; j++) {
            ull wv = reinterpret_cast<const ull*>(foA)[j];
            ulonglong2 wv2 = reinterpret_cast<const ulonglong2*>(foB)[j];
#pragma unroll
            for (int q = 0; q < R; q++) {
                float a, b;
                unpk2(hh[q][j], a, b);
                a = fmaxf(a, 0.f); b = fmaxf(b, 0.f);
                ull ab = pk2(a, a), bb = pk2(b, b);
                acc1[q] = ffma2(ab, wv, acc1[q]);
                acc2[q] = ffma2(ab, wv2.x, acc2[q]);
                acc2[q] = ffma2(bb, wv2.y, acc2[q]);
            }
        }
        float bmu0 = fb[0], esc0 = fb[1];
#pragma unroll
        for (int q = 0; q < R; q++) {
            float mu1, al1, mu2, al2;
            unpk2(acc1[q], mu1, al1); unpk2(acc2[q], mu2, al2);
            float t1 = tanh_fast(al1);                 // HW MUFU.TANH, ~1e-6 abs err
            float t2 = tanh_fast(al2);
            float nx0 = (x0[q] - bmu0) * esc0;
            float nx1 = (x1[q] - mu1) * __expf(-t1);
            float nx2 = (x2[q] - mu2) * __expf(-t2);
            x0[q] = nx2; x1[q] = nx1; x2[q] = nx0;
        }
    }

    // ---- squash + HSV + store  (sigmoid(x) = 0.5*(1+tanh(x/2))) ----
#pragma unroll
    for (int q = 0; q < R; q++) {
        int rq = rbase + q * 128;
        if (rq < B) {
            float t0 = tanh_fast(0.5f * x0[q]);
            float t1 = tanh_fast(0.5f * x1[q]);
            float t2 = tanh_fast(0.5f * x2[q]);
            // 2*pi*sigmoid(x0) = pi*(1+tanh(x0/2))
            out[3 * rq + 0] = fmaf(3.14159265358979323846f, t0, 3.14159265358979323846f);
            out[3 * rq + 1] = fmaf(0.5f, t1, 0.5f);
            out[3 * rq + 2] = fmaf(0.5f, t2, 0.5f);
        }
    }
}

extern "C" void kernel_launch(void* const* d_in, const int* in_sizes, int n_in,
                              void* d_out, int out_size) {
    (void)n_in; (void)out_size;
    const float* states   = (const float*)d_in[0];
    const float* enc_w1   = (const float*)d_in[1];
    const float* enc_b1   = (const float*)d_in[2];
    const float* enc_w2   = (const float*)d_in[3];
    const float* enc_b2   = (const float*)d_in[4];
    const float* enc_w3   = (const float*)d_in[5];
    const float* enc_b3   = (const float*)d_in[6];
    const float* proj_w   = (const float*)d_in[7];
    const float* proj_b   = (const float*)d_in[8];
    const float* flow_wh  = (const float*)d_in[9];
    const float* flow_bh  = (const float*)d_in[10];
    const float* flow_wmu = (const float*)d_in[11];
    const float* flow_bmu = (const float*)d_in[12];
    const float* flow_wa  = (const float*)d_in[13];
    const float* flow_ba  = (const float*)d_in[14];

    const int B = in_sizes[0] / 4;
    const int grid = (B + 128 * R - 1) / (128 * R);
    gsi_kernel<<<grid, 128>>>(states, enc_w1, enc_b1, enc_w2, enc_b2, enc_w3, enc_b3,
                              proj_w, proj_b, flow_wh, flow_bh, flow_wmu, flow_bmu,
                              flow_wa, flow_ba, (float*)d_out, B);
}